// round 12
// baseline (speedup 1.0000x reference)
#include <cuda_runtime.h>
#include <cuda_bf16.h>
#include <mma.h>
#include <math.h>
#include <stdint.h>

using namespace nvcuda;

#define HD    1024
#define AD    256
#define ID    2048
#define NE    8
#define NTOK  4096
#define NSLOT 8192
#define R1N   4096
#define XTK   1280   // H + A

// ================= device-global scratch (fp32 only) =================
__device__ __align__(1024) float g_rh1[(size_t)NTOK * R1N];
__device__ __align__(1024) float g_rh2[(size_t)NTOK * HD];
__device__ __align__(1024) float g_h1a[(size_t)NSLOT * ID];
__device__ __align__(1024) float g_hmid[(size_t)NSLOT * HD];
__device__ __align__(1024) float g_h1b[(size_t)NSLOT * ID];
__device__ __align__(1024) float g_y[(size_t)NSLOT * HD];
__device__ __align__(1024) float g_ap[NE * HD];
__device__ __align__(1024) float g_c1[NE * ID];
__device__ float g_probs[NTOK * NE];
__device__ float g_ent[NTOK];
__device__ int   g_topk[NTOK * 2];
__device__ int   g_slot_of_tok[NTOK * 2];
__device__ int   g_tok_of_slot[NSLOT];
__device__ int   g_expert_of_slot[NSLOT];
__device__ int   g_cnt[NE];
__device__ int   g_off[NE];
__device__ int   g_cursor[NE];

__device__ __forceinline__ void split2(float v, __nv_bfloat16& h, __nv_bfloat16& l) {
  h = __float2bfloat16(v);
  l = __float2bfloat16(v - __bfloat162float(h));
}

// ================= small kernels =================
__global__ void reset_k() {
  int i = threadIdx.x;
  if (i < NE) { g_cnt[i] = 0; g_cursor[i] = 0; }
}

__global__ void ap_k(const float* __restrict__ ae, const float* __restrict__ apw,
                     const float* __restrict__ apb) {
  int idx = blockIdx.x * blockDim.x + threadIdx.x;
  if (idx >= NE * HD) return;
  int e = idx >> 10;
  const float* a = ae + e * AD;
  const float* w = apw + (size_t)idx * AD;
  float s = 0.f;
#pragma unroll 4
  for (int d = 0; d < AD; d += 4) {
    float4 av = *(const float4*)(a + d);
    float4 wv = *(const float4*)(w + d);
    s += av.x * wv.x + av.y * wv.y + av.z * wv.z + av.w * wv.w;
  }
  g_ap[idx] = s + apb[idx];
}

__global__ void c1_k(const float* __restrict__ gw1, const float* __restrict__ gb1) {
  int idx = blockIdx.x * blockDim.x + threadIdx.x;
  if (idx >= NE * ID) return;
  int e = idx / ID;
  const float* w = gw1 + (size_t)idx * (2 * HD) + HD;
  const float* a = g_ap + e * HD;
  float s = 0.f;
#pragma unroll 4
  for (int d = 0; d < HD; d += 4) {
    float4 wv = *(const float4*)(w + d);
    float4 av = *(const float4*)(a + d);
    s += wv.x * av.x + wv.y * av.y + wv.z * av.z + wv.w * av.w;
  }
  g_c1[idx] = s + gb1[idx];
}

// ================= PROVEN fp32 SIMT GEMM (router; FFMA-ceiling bound) =====
__device__ __forceinline__ void st_tile(float (*S)[128], int lc, int lr,
                                        const float4& v0, const float4& v1) {
  S[lc + 0][lr] = v0.x; S[lc + 1][lr] = v0.y; S[lc + 2][lr] = v0.z; S[lc + 3][lr] = v0.w;
  S[lc + 4][lr] = v1.x; S[lc + 5][lr] = v1.y; S[lc + 6][lr] = v1.z; S[lc + 7][lr] = v1.w;
}

template <int FMODE>
__global__ void __launch_bounds__(256, 2)
fgemm_k(const float* __restrict__ xin, const float* __restrict__ tein,
        const float* __restrict__ W, const float* __restrict__ Bias,
        int N, int K) {
  const int m0 = blockIdx.y * 128;
  const int n0 = blockIdx.x * 128;
  const float* A0 = (FMODE == 0) ? xin : g_rh1;
  float* C = (FMODE == 0) ? g_rh1 : g_rh2;

  const int tid = threadIdx.x;
  const int lr = tid >> 1;
  const int lc = (tid & 1) << 3;
  const int tx = tid & 15;
  const int ty = tid >> 4;

  int am = m0 + lr;
  const float* arow;
  const float* arow1 = nullptr;
  if (FMODE == 0) {
    arow = A0 + (size_t)am * HD;
    arow1 = tein + (size_t)am * AD;
  } else {
    arow = A0 + (size_t)am * (size_t)K;
  }
  const float* brow = W + (size_t)(n0 + lr) * K;

  __shared__ float As[2][16][128];
  __shared__ float Bs[2][16][128];

  float acc[8][8];
#pragma unroll
  for (int i = 0; i < 8; i++)
#pragma unroll
    for (int j = 0; j < 8; j++) acc[i][j] = 0.f;

  float4 a0, a1, b0, b1;
  {
    int k = lc;
    a0 = *(const float4*)(arow + k);
    a1 = *(const float4*)(arow + k + 4);
    b0 = *(const float4*)(brow + k);
    b1 = *(const float4*)(brow + k + 4);
  }
  st_tile(As[0], lc, lr, a0, a1);
  st_tile(Bs[0], lc, lr, b0, b1);
  __syncthreads();

  const int KT = K >> 4;
  for (int kt = 0; kt < KT; kt++) {
    const int cur = kt & 1;
    if (kt + 1 < KT) {
      int k = ((kt + 1) << 4) + lc;
      if (FMODE == 0 && k >= HD) {
        const float* p = arow1 + (k - HD);
        a0 = *(const float4*)(p);
        a1 = *(const float4*)(p + 4);
      } else {
        a0 = *(const float4*)(arow + k);
        a1 = *(const float4*)(arow + k + 4);
      }
      b0 = *(const float4*)(brow + k);
      b1 = *(const float4*)(brow + k + 4);
    }
#pragma unroll
    for (int k = 0; k < 16; k++) {
      float af[8], bf[8];
      *(float4*)(af)     = *(const float4*)(&As[cur][k][ty * 8]);
      *(float4*)(af + 4) = *(const float4*)(&As[cur][k][ty * 8 + 4]);
      *(float4*)(bf)     = *(const float4*)(&Bs[cur][k][tx * 8]);
      *(float4*)(bf + 4) = *(const float4*)(&Bs[cur][k][tx * 8 + 4]);
#pragma unroll
      for (int i = 0; i < 8; i++)
#pragma unroll
        for (int j = 0; j < 8; j++)
          acc[i][j] = fmaf(af[i], bf[j], acc[i][j]);
    }
    if (kt + 1 < KT) {
      st_tile(As[cur ^ 1], lc, lr, a0, a1);
      st_tile(Bs[cur ^ 1], lc, lr, b0, b1);
    }
    __syncthreads();
  }

#pragma unroll
  for (int i = 0; i < 8; i++) {
    int mi = m0 + ty * 8 + i;
    float* crow = C + (size_t)mi * N;
#pragma unroll
    for (int j = 0; j < 8; j++) {
      int n = n0 + tx * 8 + j;
      crow[n] = fmaxf(acc[i][j] + Bias[n], 0.f);
    }
  }
}

// ================= wmma bf16x3 expert GEMM, in-kernel conversion =================
// Single-buffered smem (41KB) for 2 CTAs/SM; two-pass fp32 epilogue staging.
// MODE 2: x[tok] @ gw1[:, :H]^T + c1 -> relu -> g_h1a
// MODE 3: h1a @ gw2^T + gb2 -> sigmoid mix -> g_hmid
// MODE 4: hmid @ fw1^T + fb1 -> relu -> g_h1b
// MODE 5: h1b @ fw2^T + fb2 + x -> g_y
#define PITCH  40                      // bf16 elems per smem row (32 + 8 pad)
#define TSZ    (128 * PITCH)           // elems per 128x32 tile
#define AHO    0
#define ALO    (1 * TSZ)
#define BHO    (2 * TSZ)
#define BLO    (3 * TSZ)
#define CP2    68                      // fp32 epilogue pitch (64 + 4 pad)
#define SMEM_DYN (4 * TSZ * 2 + 1024)  // 40960B buffer (csm 128*68*4=34816 overlaps)

template <int MODE>
__global__ void __launch_bounds__(256, 2)
mgemm_k(const float* __restrict__ W, const float* __restrict__ Bias,
        const float* __restrict__ xin, long wstride) {
  constexpr int N = (MODE == 2 || MODE == 4) ? ID : HD;
  constexpr int K = (MODE == 3 || MODE == 5) ? ID : HD;
  constexpr int KT = K >> 5;

  const int e = blockIdx.z;
  const int mcount = g_cnt[e];
  const int moff = g_off[e];
  const int m0 = blockIdx.y * 128;
  if (m0 >= mcount) return;
  const int n0 = blockIdx.x * 128;

  extern __shared__ char dsm[];
  char* dynp = (char*)(((uintptr_t)dsm + 1023) & ~(uintptr_t)1023);
  __nv_bfloat16* smb = (__nv_bfloat16*)dynp;
  float* csm = (float*)dynp;

  const int tid = threadIdx.x;
  const int wid = tid >> 5;
  const int lrow = tid >> 1;
  const int colb = (tid & 1) << 4;

  // ---- fp32 global row pointers ----
  int am = m0 + lrow;
  if (am >= mcount) am = mcount - 1;
  const int aslot = moff + am;
  const float* arow;
  if (MODE == 2)      arow = xin + (size_t)g_tok_of_slot[aslot] * HD;
  else if (MODE == 3) arow = g_h1a + (size_t)aslot * ID;
  else if (MODE == 4) arow = g_hmid + (size_t)aslot * HD;
  else                arow = g_h1b + (size_t)aslot * ID;
  const float* brow = W + ((size_t)e * N + n0 + lrow) * (size_t)wstride;

  float4 ar[4], br[4];

#define LOADR(kbase) do { \
  int k0_ = (kbase) + colb; \
  _Pragma("unroll") \
  for (int q = 0; q < 4; q++) { \
    ar[q] = *(const float4*)(arow + k0_ + q * 4); \
    br[q] = *(const float4*)(brow + k0_ + q * 4); \
  } \
} while (0)

#define STORES() do { \
  __nv_bfloat16* bs_ = smb + lrow * PITCH + colb; \
  const float* af_ = (const float*)ar; \
  const float* bf_ = (const float*)br; \
  _Pragma("unroll") \
  for (int i = 0; i < 16; i += 2) { \
    __nv_bfloat16 h0, l0, h1, l1; \
    split2(af_[i], h0, l0); split2(af_[i + 1], h1, l1); \
    *(__nv_bfloat162*)(bs_ + AHO + i) = __nv_bfloat162(h0, h1); \
    *(__nv_bfloat162*)(bs_ + ALO + i) = __nv_bfloat162(l0, l1); \
    split2(bf_[i], h0, l0); split2(bf_[i + 1], h1, l1); \
    *(__nv_bfloat162*)(bs_ + BHO + i) = __nv_bfloat162(h0, h1); \
    *(__nv_bfloat162*)(bs_ + BLO + i) = __nv_bfloat162(l0, l1); \
  } \
} while (0)

  // ---- wmma tiling: 8 warps = 2(m) x 4(n); warp tile 64m x 32n ----
  const int wm = wid & 1;
  const int wn = wid >> 1;

  wmma::fragment<wmma::accumulator, 16, 16, 16, float> cf[4][2];
#pragma unroll
  for (int mt = 0; mt < 4; mt++)
#pragma unroll
    for (int nt = 0; nt < 2; nt++) wmma::fill_fragment(cf[mt][nt], 0.f);

  LOADR(0);

  for (int c = 0; c < KT; c++) {
    STORES();                    // regs(chunk c) -> smem
    __syncthreads();
    if (c + 1 < KT) LOADR((c + 1) << 5);   // LDG next chunk; overlaps MMA
#pragma unroll
    for (int ks = 0; ks < 2; ks++) {
      wmma::fragment<wmma::matrix_b, 16, 16, 16, __nv_bfloat16, wmma::col_major> bh[2], bl[2];
#pragma unroll
      for (int nt = 0; nt < 2; nt++) {
        const int bo = (wn * 32 + nt * 16) * PITCH + ks * 16;
        wmma::load_matrix_sync(bh[nt], smb + BHO + bo, PITCH);
        wmma::load_matrix_sync(bl[nt], smb + BLO + bo, PITCH);
      }
#pragma unroll
      for (int mt = 0; mt < 4; mt++) {
        const int ao = (wm * 64 + mt * 16) * PITCH + ks * 16;
        wmma::fragment<wmma::matrix_a, 16, 16, 16, __nv_bfloat16, wmma::row_major> ah, al;
        wmma::load_matrix_sync(ah, smb + AHO + ao, PITCH);
        wmma::load_matrix_sync(al, smb + ALO + ao, PITCH);
#pragma unroll
        for (int nt = 0; nt < 2; nt++) {
          wmma::mma_sync(cf[mt][nt], ah, bh[nt], cf[mt][nt]);
          wmma::mma_sync(cf[mt][nt], al, bh[nt], cf[mt][nt]);
          wmma::mma_sync(cf[mt][nt], ah, bl[nt], cf[mt][nt]);
        }
      }
    }
    __syncthreads();             // all reads of smb done before next STORES
  }

  // ---- two-pass epilogue: 64 columns at a time through fp32 smem ----
  const float* bias;
  if (MODE == 2)      bias = g_c1 + e * ID;
  else if (MODE == 3) bias = Bias + (size_t)e * HD;
  else if (MODE == 4) bias = Bias + (size_t)e * ID;
  else                bias = Bias + (size_t)e * HD;

  const int r = tid >> 1;
  const int ch = tid & 1;           // 32-col half within the 64-col pass
  const int mi = m0 + r;
  const bool valid = (mi < mcount);
  const int slot = moff + (valid ? mi : 0);
  const int tok = g_tok_of_slot[slot];

#pragma unroll
  for (int hf = 0; hf < 2; hf++) {
    // warps with wn in {hf*2, hf*2+1} own columns [hf*64, hf*64+64)
    if ((wn >> 1) == hf) {
      const int wnl = wn & 1;       // 0/1 within this half
#pragma unroll
      for (int mt = 0; mt < 4; mt++)
#pragma unroll
        for (int nt = 0; nt < 2; nt++)
          wmma::store_matrix_sync(csm + (wm * 64 + mt * 16) * CP2 + wnl * 32 + nt * 16,
                                  cf[mt][nt], CP2, wmma::mem_row_major);
    }
    __syncthreads();
    if (valid) {
      const float* crow = csm + r * CP2 + ch * 32;
      const int nb = n0 + hf * 64 + ch * 32;
#pragma unroll
      for (int j = 0; j < 32; j++) {
        const int n = nb + j;
        float v = crow[j] + bias[n];
        if (MODE == 2) {
          g_h1a[(size_t)slot * ID + n] = fmaxf(v, 0.f);
        } else if (MODE == 3) {
          float g = 1.f / (1.f + expf(-v));
          float xv = xin[(size_t)tok * HD + n];
          float apv = g_ap[e * HD + n];
          g_hmid[(size_t)slot * HD + n] = xv * g + apv * (1.f - g);
        } else if (MODE == 4) {
          g_h1b[(size_t)slot * ID + n] = fmaxf(v, 0.f);
        } else {
          g_y[(size_t)slot * HD + n] = v + xin[(size_t)tok * HD + n];
        }
      }
    }
    if (hf == 0) __syncthreads();
  }
}

// ================= router head / routing / LN / combine / loss =================
__global__ void router_head_k(const float* __restrict__ te,
                              const float* __restrict__ r_attr,
                              const float* __restrict__ r_w,
                              const float* __restrict__ r_b) {
  int t = blockIdx.x;
  int tid = threadIdx.x;
  const float* hrow = g_rh2 + (size_t)t * HD;
  float pe[NE];
#pragma unroll
  for (int e = 0; e < NE; e++) pe[e] = 0.f;
  for (int k = tid; k < HD; k += 256) {
    float hv = hrow[k];
#pragma unroll
    for (int e = 0; e < NE; e++) pe[e] = fmaf(hv, r_w[e * HD + k], pe[e]);
  }
#pragma unroll
  for (int e = 0; e < NE; e++)
    for (int o = 16; o > 0; o >>= 1) pe[e] += __shfl_xor_sync(0xffffffffu, pe[e], o);
  __shared__ float sw[NE][8];
  int w = tid >> 5;
  if ((tid & 31) == 0)
#pragma unroll
    for (int e = 0; e < NE; e++) sw[e][w] = pe[e];
  __syncthreads();
  if (tid == 0) {
    float lg[NE];
    float mx = -1e30f;
    for (int e = 0; e < NE; e++) {
      float s = 0.f;
      for (int i = 0; i < 8; i++) s += sw[e][i];
      s += r_b[e];
      lg[e] = s;
      if (s > mx) mx = s;
    }
    float se = 0.f;
    for (int e = 0; e < NE; e++) { lg[e] = expf(lg[e] - mx); se += lg[e]; }
    float inv = 1.f / se;

    float attr[NE];
    for (int e = 0; e < NE; e++) attr[e] = 0.f;
    const float* tr = te + (size_t)t * AD;
    for (int n = 0; n < 4; n++) {
      float sc[NE];
      for (int e = 0; e < NE; e++) sc[e] = 0.f;
      for (int d = 0; d < 64; d++) {
        float tv = tr[n * 64 + d];
#pragma unroll
        for (int e = 0; e < NE; e++) sc[e] = fmaf(tv, r_attr[d * NE + e], sc[e]);
      }
      float m2 = -1e30f;
      for (int e = 0; e < NE; e++) if (sc[e] > m2) m2 = sc[e];
      float ss = 0.f;
      for (int e = 0; e < NE; e++) { sc[e] = expf(sc[e] - m2); ss += sc[e]; }
      float rr = 0.25f / ss;
      for (int e = 0; e < NE; e++) attr[e] += sc[e] * rr;
    }

    float p[NE];
    for (int e = 0; e < NE; e++) p[e] = lg[e] * inv * attr[e];
    int i0 = 0;
    for (int e = 1; e < NE; e++) if (p[e] > p[i0]) i0 = e;
    int i1 = (i0 == 0) ? 1 : 0;
    for (int e = 0; e < NE; e++) if (e != i0 && p[e] > p[i1]) i1 = e;

    for (int e = 0; e < NE; e++)
      g_probs[t * NE + e] = (e == i0 || e == i1) ? p[e] : 0.f;
    float p0 = p[i0], p1 = p[i1];
    g_ent[t] = p0 * logf(p0 + 1e-8f) + p1 * logf(p1 + 1e-8f);
    int elo = i0 < i1 ? i0 : i1;
    int ehi = i0 < i1 ? i1 : i0;
    g_topk[2 * t] = elo;
    g_topk[2 * t + 1] = ehi;
    atomicAdd(&g_cnt[elo], 1);
    atomicAdd(&g_cnt[ehi], 1);
  }
}

__global__ void offsets_k() {
  if (threadIdx.x == 0) {
    int o = 0;
    for (int e = 0; e < NE; e++) { g_off[e] = o; o += g_cnt[e]; }
  }
}

__global__ void assign_k() {
  int t = blockIdx.x * blockDim.x + threadIdx.x;
  if (t >= NTOK) return;
#pragma unroll
  for (int k = 0; k < 2; k++) {
    int e = g_topk[2 * t + k];
    int slot = g_off[e] + atomicAdd(&g_cursor[e], 1);
    g_tok_of_slot[slot] = t;
    g_expert_of_slot[slot] = e;
    g_slot_of_tok[2 * t + k] = slot;
  }
}

__global__ void ln_k(const float* __restrict__ lng, const float* __restrict__ lnb) {
  int s = blockIdx.x;
  int e = g_expert_of_slot[s];
  float* row = g_y + (size_t)s * HD;
  int tid = threadIdx.x;
  float4 v = *(const float4*)(row + tid * 4);
  float sum = v.x + v.y + v.z + v.w;
  float sq = v.x * v.x + v.y * v.y + v.z * v.z + v.w * v.w;
  for (int o = 16; o > 0; o >>= 1) {
    sum += __shfl_xor_sync(0xffffffffu, sum, o);
    sq += __shfl_xor_sync(0xffffffffu, sq, o);
  }
  __shared__ float s1[8], s2[8];
  int w = tid >> 5;
  if ((tid & 31) == 0) { s1[w] = sum; s2[w] = sq; }
  __syncthreads();
  float ts = 0.f, tq = 0.f;
#pragma unroll
  for (int i = 0; i < 8; i++) { ts += s1[i]; tq += s2[i]; }
  float mu = ts * (1.f / HD);
  float var = tq * (1.f / HD) - mu * mu;
  float rstd = rsqrtf(var + 1e-5f);
  const float4 g4 = *(const float4*)(lng + e * HD + tid * 4);
  const float4 b4 = *(const float4*)(lnb + e * HD + tid * 4);
  float4 o;
  o.x = (v.x - mu) * rstd * g4.x + b4.x;
  o.y = (v.y - mu) * rstd * g4.y + b4.y;
  o.z = (v.z - mu) * rstd * g4.z + b4.z;
  o.w = (v.w - mu) * rstd * g4.w + b4.w;
  *(float4*)(row + tid * 4) = o;
}

__global__ void combine_k(float* __restrict__ out) {
  int t = blockIdx.x;
  int tid = threadIdx.x;
  int s0 = g_slot_of_tok[2 * t], s1 = g_slot_of_tok[2 * t + 1];
  int e0 = g_topk[2 * t], e1 = g_topk[2 * t + 1];
  float p0 = g_probs[t * NE + e0], p1 = g_probs[t * NE + e1];
  const float4 y0 = *(const float4*)(g_y + (size_t)s0 * HD + tid * 4);
  const float4 y1 = *(const float4*)(g_y + (size_t)s1 * HD + tid * 4);
  float4 o;
  o.x = p0 * y0.x + p1 * y1.x;
  o.y = p0 * y0.y + p1 * y1.y;
  o.z = p0 * y0.z + p1 * y1.z;
  o.w = p0 * y0.w + p1 * y1.w;
  *(float4*)(out + (size_t)t * HD + tid * 4) = o;
}

__global__ void loss_k(float* __restrict__ out, int out_size) {
  __shared__ float red[256];
  float s = 0.f;
  for (int i = threadIdx.x; i < NTOK; i += 256) s += g_ent[i];
  red[threadIdx.x] = s;
  __syncthreads();
  for (int o = 128; o > 0; o >>= 1) {
    if (threadIdx.x < o) red[threadIdx.x] += red[threadIdx.x + o];
    __syncthreads();
  }
  if (threadIdx.x == 0) {
    float loss = -red[0] / (float)NTOK;
    for (int i = NTOK * HD; i < out_size; i++) out[i] = loss;
  }
}

// ================= launch =================
extern "C" void kernel_launch(void* const* d_in, const int* in_sizes, int n_in,
                              void* d_out, int out_size) {
  const float* x           = (const float*)d_in[0];
  const float* te          = (const float*)d_in[1];
  const float* attr_emb    = (const float*)d_in[2];
  const float* attr_proj_w = (const float*)d_in[3];
  const float* attr_proj_b = (const float*)d_in[4];
  const float* gate_w1     = (const float*)d_in[5];
  const float* gate_b1     = (const float*)d_in[6];
  const float* gate_w2     = (const float*)d_in[7];
  const float* gate_b2     = (const float*)d_in[8];
  const float* fc_w1       = (const float*)d_in[9];
  const float* fc_b1       = (const float*)d_in[10];
  const float* fc_w2       = (const float*)d_in[11];
  const float* fc_b2       = (const float*)d_in[12];
  const float* ln_g        = (const float*)d_in[13];
  const float* ln_b        = (const float*)d_in[14];
  const float* r_attr      = (const float*)d_in[15];
  const float* r_in_w      = (const float*)d_in[16];
  const float* r_in_b      = (const float*)d_in[17];
  const float* r_mid_w     = (const float*)d_in[18];
  const float* r_mid_b     = (const float*)d_in[19];
  const float* r_w         = (const float*)d_in[20];
  const float* r_b         = (const float*)d_in[21];
  float* out = (float*)d_out;

  cudaFuncSetAttribute(mgemm_k<2>, cudaFuncAttributeMaxDynamicSharedMemorySize, SMEM_DYN);
  cudaFuncSetAttribute(mgemm_k<3>, cudaFuncAttributeMaxDynamicSharedMemorySize, SMEM_DYN);
  cudaFuncSetAttribute(mgemm_k<4>, cudaFuncAttributeMaxDynamicSharedMemorySize, SMEM_DYN);
  cudaFuncSetAttribute(mgemm_k<5>, cudaFuncAttributeMaxDynamicSharedMemorySize, SMEM_DYN);

  reset_k<<<1, 32>>>();
  ap_k<<<(NE * HD + 255) / 256, 256>>>(attr_emb, attr_proj_w, attr_proj_b);
  c1_k<<<(NE * ID + 255) / 256, 256>>>(gate_w1, gate_b1);

  // router MLP — exact fp32 (protects top-2 decisions; FFMA-ceiling bound)
  fgemm_k<0><<<dim3(R1N / 128, NTOK / 128, 1), 256>>>(x, te, r_in_w, r_in_b, R1N, XTK);
  fgemm_k<1><<<dim3(HD / 128, NTOK / 128, 1), 256>>>(nullptr, nullptr, r_mid_w, r_mid_b, HD, R1N);
  router_head_k<<<NTOK, 256>>>(te, r_attr, r_w, r_b);
  offsets_k<<<1, 32>>>();
  assign_k<<<NTOK / 256, 256>>>();

  // expert FFNs — bf16x3 wmma, in-kernel conversion, single-buffer smem
  mgemm_k<2><<<dim3(ID / 128, NTOK / 128, NE), 256, SMEM_DYN>>>(gate_w1, gate_b1, x, 2 * HD);
  mgemm_k<3><<<dim3(HD / 128, NTOK / 128, NE), 256, SMEM_DYN>>>(gate_w2, gate_b2, x, ID);
  mgemm_k<4><<<dim3(ID / 128, NTOK / 128, NE), 256, SMEM_DYN>>>(fc_w1, fc_b1, x, HD);
  mgemm_k<5><<<dim3(HD / 128, NTOK / 128, NE), 256, SMEM_DYN>>>(fc_w2, fc_b2, x, ID);

  ln_k<<<NSLOT, 256>>>(ln_g, ln_b);
  combine_k<<<NTOK, 256>>>(out);
  loss_k<<<1, 256>>>(out, out_size);
}

// round 13
// speedup vs baseline: 1.2063x; 1.2063x over previous
#include <cuda_runtime.h>
#include <cuda_bf16.h>
#include <mma.h>
#include <math.h>
#include <stdint.h>

using namespace nvcuda;

#define HD    1024
#define AD    256
#define ID    2048
#define NE    8
#define NTOK  4096
#define NSLOT 8192
#define R1N   4096
#define XTK   1280   // H + A

// ================= device-global scratch (fp32 only) =================
__device__ __align__(1024) float g_rh1[(size_t)NTOK * R1N];
__device__ __align__(1024) float g_rh2[(size_t)NTOK * HD];
__device__ __align__(1024) float g_h1a[(size_t)NSLOT * ID];
__device__ __align__(1024) float g_hmid[(size_t)NSLOT * HD];
__device__ __align__(1024) float g_h1b[(size_t)NSLOT * ID];
__device__ __align__(1024) float g_y[(size_t)NSLOT * HD];
__device__ __align__(1024) float g_ap[NE * HD];
__device__ __align__(1024) float g_c1[NE * ID];
__device__ float g_probs[NTOK * NE];
__device__ float g_ent[NTOK];
__device__ int   g_topk[NTOK * 2];
__device__ int   g_slot_of_tok[NTOK * 2];
__device__ int   g_tok_of_slot[NSLOT];
__device__ int   g_expert_of_slot[NSLOT];
__device__ int   g_cnt[NE];
__device__ int   g_off[NE];
__device__ int   g_cursor[NE];

__device__ __forceinline__ void split2(float v, __nv_bfloat16& h, __nv_bfloat16& l) {
  h = __float2bfloat16(v);
  l = __float2bfloat16(v - __bfloat162float(h));
}

// ================= small kernels =================
__global__ void reset_k() {
  int i = threadIdx.x;
  if (i < NE) { g_cnt[i] = 0; g_cursor[i] = 0; }
}

__global__ void ap_k(const float* __restrict__ ae, const float* __restrict__ apw,
                     const float* __restrict__ apb) {
  int idx = blockIdx.x * blockDim.x + threadIdx.x;
  if (idx >= NE * HD) return;
  int e = idx >> 10;
  const float* a = ae + e * AD;
  const float* w = apw + (size_t)idx * AD;
  float s = 0.f;
#pragma unroll 4
  for (int d = 0; d < AD; d += 4) {
    float4 av = *(const float4*)(a + d);
    float4 wv = *(const float4*)(w + d);
    s += av.x * wv.x + av.y * wv.y + av.z * wv.z + av.w * wv.w;
  }
  g_ap[idx] = s + apb[idx];
}

__global__ void c1_k(const float* __restrict__ gw1, const float* __restrict__ gb1) {
  int idx = blockIdx.x * blockDim.x + threadIdx.x;
  if (idx >= NE * ID) return;
  int e = idx / ID;
  const float* w = gw1 + (size_t)idx * (2 * HD) + HD;
  const float* a = g_ap + e * HD;
  float s = 0.f;
#pragma unroll 4
  for (int d = 0; d < HD; d += 4) {
    float4 wv = *(const float4*)(w + d);
    float4 av = *(const float4*)(a + d);
    s += wv.x * av.x + wv.y * av.y + wv.z * av.z + wv.w * av.w;
  }
  g_c1[idx] = s + gb1[idx];
}

// ================= PROVEN fp32 SIMT GEMM (router; FFMA-ceiling bound) =====
__device__ __forceinline__ void st_tile(float (*S)[128], int lc, int lr,
                                        const float4& v0, const float4& v1) {
  S[lc + 0][lr] = v0.x; S[lc + 1][lr] = v0.y; S[lc + 2][lr] = v0.z; S[lc + 3][lr] = v0.w;
  S[lc + 4][lr] = v1.x; S[lc + 5][lr] = v1.y; S[lc + 6][lr] = v1.z; S[lc + 7][lr] = v1.w;
}

template <int FMODE>
__global__ void __launch_bounds__(256, 2)
fgemm_k(const float* __restrict__ xin, const float* __restrict__ tein,
        const float* __restrict__ W, const float* __restrict__ Bias,
        int N, int K) {
  const int m0 = blockIdx.y * 128;
  const int n0 = blockIdx.x * 128;
  const float* A0 = (FMODE == 0) ? xin : g_rh1;
  float* C = (FMODE == 0) ? g_rh1 : g_rh2;

  const int tid = threadIdx.x;
  const int lr = tid >> 1;
  const int lc = (tid & 1) << 3;
  const int tx = tid & 15;
  const int ty = tid >> 4;

  int am = m0 + lr;
  const float* arow;
  const float* arow1 = nullptr;
  if (FMODE == 0) {
    arow = A0 + (size_t)am * HD;
    arow1 = tein + (size_t)am * AD;
  } else {
    arow = A0 + (size_t)am * (size_t)K;
  }
  const float* brow = W + (size_t)(n0 + lr) * K;

  __shared__ float As[2][16][128];
  __shared__ float Bs[2][16][128];

  float acc[8][8];
#pragma unroll
  for (int i = 0; i < 8; i++)
#pragma unroll
    for (int j = 0; j < 8; j++) acc[i][j] = 0.f;

  float4 a0, a1, b0, b1;
  {
    int k = lc;
    a0 = *(const float4*)(arow + k);
    a1 = *(const float4*)(arow + k + 4);
    b0 = *(const float4*)(brow + k);
    b1 = *(const float4*)(brow + k + 4);
  }
  st_tile(As[0], lc, lr, a0, a1);
  st_tile(Bs[0], lc, lr, b0, b1);
  __syncthreads();

  const int KT = K >> 4;
  for (int kt = 0; kt < KT; kt++) {
    const int cur = kt & 1;
    if (kt + 1 < KT) {
      int k = ((kt + 1) << 4) + lc;
      if (FMODE == 0 && k >= HD) {
        const float* p = arow1 + (k - HD);
        a0 = *(const float4*)(p);
        a1 = *(const float4*)(p + 4);
      } else {
        a0 = *(const float4*)(arow + k);
        a1 = *(const float4*)(arow + k + 4);
      }
      b0 = *(const float4*)(brow + k);
      b1 = *(const float4*)(brow + k + 4);
    }
#pragma unroll
    for (int k = 0; k < 16; k++) {
      float af[8], bf[8];
      *(float4*)(af)     = *(const float4*)(&As[cur][k][ty * 8]);
      *(float4*)(af + 4) = *(const float4*)(&As[cur][k][ty * 8 + 4]);
      *(float4*)(bf)     = *(const float4*)(&Bs[cur][k][tx * 8]);
      *(float4*)(bf + 4) = *(const float4*)(&Bs[cur][k][tx * 8 + 4]);
#pragma unroll
      for (int i = 0; i < 8; i++)
#pragma unroll
        for (int j = 0; j < 8; j++)
          acc[i][j] = fmaf(af[i], bf[j], acc[i][j]);
    }
    if (kt + 1 < KT) {
      st_tile(As[cur ^ 1], lc, lr, a0, a1);
      st_tile(Bs[cur ^ 1], lc, lr, b0, b1);
    }
    __syncthreads();
  }

#pragma unroll
  for (int i = 0; i < 8; i++) {
    int mi = m0 + ty * 8 + i;
    float* crow = C + (size_t)mi * N;
#pragma unroll
    for (int j = 0; j < 8; j++) {
      int n = n0 + tx * 8 + j;
      crow[n] = fmaxf(acc[i][j] + Bias[n], 0.f);
    }
  }
}

// ================= wmma bf16x3 expert GEMM, 128x256 tile, in-kernel conv ========
// Double-buffered smem; warp tile 64x64 (2x compute per LDSM vs 64x32).
// MODE 2: x[tok] @ gw1[:, :H]^T + c1 -> relu -> g_h1a
// MODE 3: h1a @ gw2^T + gb2 -> sigmoid mix -> g_hmid
// MODE 4: hmid @ fw1^T + fb1 -> relu -> g_h1b
// MODE 5: h1b @ fw2^T + fb2 + x -> g_y
#define PITCH  40                       // bf16 elems per smem row (32 + 8 pad)
#define AHO    0                        // A-hi: 128 rows
#define ALO    (128 * PITCH)            // A-lo
#define BHO    (256 * PITCH)            // B-hi: 256 rows
#define BLO    (512 * PITCH)            // B-lo
#define SSE    (768 * PITCH)            // stage elems (30720) = 61440 B
#define CP2    132                      // fp32 epilogue pitch (128 + 4 pad)
#define SMEM_DYN (2 * SSE * 2 + 1024)   // 122880 B + align (csm 67584 B overlaps)

template <int MODE>
__global__ void __launch_bounds__(256, 1)
mgemm_k(const float* __restrict__ W, const float* __restrict__ Bias,
        const float* __restrict__ xin, long wstride) {
  constexpr int N = (MODE == 2 || MODE == 4) ? ID : HD;
  constexpr int K = (MODE == 3 || MODE == 5) ? ID : HD;
  constexpr int KT = K >> 5;

  const int e = blockIdx.z;
  const int mcount = g_cnt[e];
  const int moff = g_off[e];
  const int m0 = blockIdx.y * 128;
  if (m0 >= mcount) return;
  const int n0 = blockIdx.x * 256;

  extern __shared__ char dsm[];
  char* dynp = (char*)(((uintptr_t)dsm + 1023) & ~(uintptr_t)1023);
  __nv_bfloat16* smb = (__nv_bfloat16*)dynp;
  float* csm = (float*)dynp;

  const int tid = threadIdx.x;
  const int wid = tid >> 5;
  const int lrow = tid >> 1;          // 0..127
  const int colb = (tid & 1) << 4;    // 0 or 16

  // ---- fp32 global row pointers ----
  int am = m0 + lrow;
  if (am >= mcount) am = mcount - 1;
  const int aslot = moff + am;
  const float* arow;
  if (MODE == 2)      arow = xin + (size_t)g_tok_of_slot[aslot] * HD;
  else if (MODE == 3) arow = g_h1a + (size_t)aslot * ID;
  else if (MODE == 4) arow = g_hmid + (size_t)aslot * HD;
  else                arow = g_h1b + (size_t)aslot * ID;
  const float* brow0 = W + ((size_t)e * N + n0 + lrow) * (size_t)wstride;
  const float* brow1 = brow0 + (size_t)128 * wstride;

  float4 ar[4], br0[4], br1[4];

#define LOADR(kbase) do { \
  int k0_ = (kbase) + colb; \
  _Pragma("unroll") \
  for (int q = 0; q < 4; q++) { \
    ar[q]  = *(const float4*)(arow  + k0_ + q * 4); \
    br0[q] = *(const float4*)(brow0 + k0_ + q * 4); \
    br1[q] = *(const float4*)(brow1 + k0_ + q * 4); \
  } \
} while (0)

#define SPLIT16(srcp, dsth, dstl) do { \
  const float* f_ = (const float*)(srcp); \
  _Pragma("unroll") \
  for (int i = 0; i < 16; i += 2) { \
    __nv_bfloat16 h0, l0, h1, l1; \
    split2(f_[i], h0, l0); split2(f_[i + 1], h1, l1); \
    *(__nv_bfloat162*)((dsth) + i) = __nv_bfloat162(h0, h1); \
    *(__nv_bfloat162*)((dstl) + i) = __nv_bfloat162(l0, l1); \
  } \
} while (0)

#define STORES(stage) do { \
  __nv_bfloat16* s_ = smb + (stage) * SSE; \
  __nv_bfloat16* as_ = s_ + lrow * PITCH + colb; \
  SPLIT16(ar, as_ + AHO, as_ + ALO); \
  __nv_bfloat16* b0_ = s_ + BHO + lrow * PITCH + colb; \
  SPLIT16(br0, b0_, b0_ + (BLO - BHO)); \
  __nv_bfloat16* b1_ = s_ + BHO + (128 + lrow) * PITCH + colb; \
  SPLIT16(br1, b1_, b1_ + (BLO - BHO)); \
} while (0)

  // ---- wmma tiling: 8 warps = 2(m) x 4(n); warp tile 64m x 64n ----
  const int wm = wid & 1;
  const int wn = wid >> 1;

  wmma::fragment<wmma::accumulator, 16, 16, 16, float> cf[4][4];
#pragma unroll
  for (int mt = 0; mt < 4; mt++)
#pragma unroll
    for (int nt = 0; nt < 4; nt++) wmma::fill_fragment(cf[mt][nt], 0.f);

  LOADR(0);
  STORES(0);
  __syncthreads();

  for (int c = 0; c < KT; c++) {
    if (c + 1 < KT) LOADR((c + 1) << 5);
    const __nv_bfloat16* sb = smb + (c & 1) * SSE;
#pragma unroll
    for (int ks = 0; ks < 2; ks++) {
      wmma::fragment<wmma::matrix_b, 16, 16, 16, __nv_bfloat16, wmma::col_major> bh[4], bl[4];
#pragma unroll
      for (int nt = 0; nt < 4; nt++) {
        const int bo = (wn * 64 + nt * 16) * PITCH + ks * 16;
        wmma::load_matrix_sync(bh[nt], sb + BHO + bo, PITCH);
        wmma::load_matrix_sync(bl[nt], sb + BLO + bo, PITCH);
      }
#pragma unroll
      for (int mt = 0; mt < 4; mt++) {
        const int ao = (wm * 64 + mt * 16) * PITCH + ks * 16;
        wmma::fragment<wmma::matrix_a, 16, 16, 16, __nv_bfloat16, wmma::row_major> ah, al;
        wmma::load_matrix_sync(ah, sb + AHO + ao, PITCH);
        wmma::load_matrix_sync(al, sb + ALO + ao, PITCH);
#pragma unroll
        for (int nt = 0; nt < 4; nt++) {
          wmma::mma_sync(cf[mt][nt], ah, bh[nt], cf[mt][nt]);
          wmma::mma_sync(cf[mt][nt], al, bh[nt], cf[mt][nt]);
          wmma::mma_sync(cf[mt][nt], ah, bl[nt], cf[mt][nt]);
        }
      }
    }
    if (c + 1 < KT) STORES((c + 1) & 1);
    __syncthreads();
  }

  // ---- two-pass epilogue: 128 columns at a time through fp32 smem ----
  const float* bias;
  if (MODE == 2)      bias = g_c1 + e * ID;
  else if (MODE == 3) bias = Bias + (size_t)e * HD;
  else if (MODE == 4) bias = Bias + (size_t)e * ID;
  else                bias = Bias + (size_t)e * HD;

  const int r = tid >> 1;
  const int ch = tid & 1;
  const int mi = m0 + r;
  const bool valid = (mi < mcount);
  const int slot = moff + (valid ? mi : 0);
  const int tok = g_tok_of_slot[slot];

#pragma unroll
  for (int hf = 0; hf < 2; hf++) {
    // warps with (wn>>1)==hf own columns [hf*128, hf*128+128)
    if ((wn >> 1) == hf) {
      const int wnl = wn & 1;  // 0/1 -> 64-col block within this half
#pragma unroll
      for (int mt = 0; mt < 4; mt++)
#pragma unroll
        for (int nt = 0; nt < 4; nt++)
          wmma::store_matrix_sync(csm + (wm * 64 + mt * 16) * CP2 + wnl * 64 + nt * 16,
                                  cf[mt][nt], CP2, wmma::mem_row_major);
    }
    __syncthreads();
    if (valid) {
      const float* crow = csm + r * CP2 + ch * 64;
      const int nb = n0 + hf * 128 + ch * 64;
#pragma unroll
      for (int j = 0; j < 64; j++) {
        const int n = nb + j;
        float v = crow[j] + bias[n];
        if (MODE == 2) {
          g_h1a[(size_t)slot * ID + n] = fmaxf(v, 0.f);
        } else if (MODE == 3) {
          float g = 1.f / (1.f + expf(-v));
          float xv = xin[(size_t)tok * HD + n];
          float apv = g_ap[e * HD + n];
          g_hmid[(size_t)slot * HD + n] = xv * g + apv * (1.f - g);
        } else if (MODE == 4) {
          g_h1b[(size_t)slot * ID + n] = fmaxf(v, 0.f);
        } else {
          g_y[(size_t)slot * HD + n] = v + xin[(size_t)tok * HD + n];
        }
      }
    }
    if (hf == 0) __syncthreads();
  }
}

// ================= router head / routing / LN / combine / loss =================
__global__ void router_head_k(const float* __restrict__ te,
                              const float* __restrict__ r_attr,
                              const float* __restrict__ r_w,
                              const float* __restrict__ r_b) {
  int t = blockIdx.x;
  int tid = threadIdx.x;
  const float* hrow = g_rh2 + (size_t)t * HD;
  float pe[NE];
#pragma unroll
  for (int e = 0; e < NE; e++) pe[e] = 0.f;
  for (int k = tid; k < HD; k += 256) {
    float hv = hrow[k];
#pragma unroll
    for (int e = 0; e < NE; e++) pe[e] = fmaf(hv, r_w[e * HD + k], pe[e]);
  }
#pragma unroll
  for (int e = 0; e < NE; e++)
    for (int o = 16; o > 0; o >>= 1) pe[e] += __shfl_xor_sync(0xffffffffu, pe[e], o);
  __shared__ float sw[NE][8];
  int w = tid >> 5;
  if ((tid & 31) == 0)
#pragma unroll
    for (int e = 0; e < NE; e++) sw[e][w] = pe[e];
  __syncthreads();
  if (tid == 0) {
    float lg[NE];
    float mx = -1e30f;
    for (int e = 0; e < NE; e++) {
      float s = 0.f;
      for (int i = 0; i < 8; i++) s += sw[e][i];
      s += r_b[e];
      lg[e] = s;
      if (s > mx) mx = s;
    }
    float se = 0.f;
    for (int e = 0; e < NE; e++) { lg[e] = expf(lg[e] - mx); se += lg[e]; }
    float inv = 1.f / se;

    float attr[NE];
    for (int e = 0; e < NE; e++) attr[e] = 0.f;
    const float* tr = te + (size_t)t * AD;
    for (int n = 0; n < 4; n++) {
      float sc[NE];
      for (int e = 0; e < NE; e++) sc[e] = 0.f;
      for (int d = 0; d < 64; d++) {
        float tv = tr[n * 64 + d];
#pragma unroll
        for (int e = 0; e < NE; e++) sc[e] = fmaf(tv, r_attr[d * NE + e], sc[e]);
      }
      float m2 = -1e30f;
      for (int e = 0; e < NE; e++) if (sc[e] > m2) m2 = sc[e];
      float ss = 0.f;
      for (int e = 0; e < NE; e++) { sc[e] = expf(sc[e] - m2); ss += sc[e]; }
      float rr = 0.25f / ss;
      for (int e = 0; e < NE; e++) attr[e] += sc[e] * rr;
    }

    float p[NE];
    for (int e = 0; e < NE; e++) p[e] = lg[e] * inv * attr[e];
    int i0 = 0;
    for (int e = 1; e < NE; e++) if (p[e] > p[i0]) i0 = e;
    int i1 = (i0 == 0) ? 1 : 0;
    for (int e = 0; e < NE; e++) if (e != i0 && p[e] > p[i1]) i1 = e;

    for (int e = 0; e < NE; e++)
      g_probs[t * NE + e] = (e == i0 || e == i1) ? p[e] : 0.f;
    float p0 = p[i0], p1 = p[i1];
    g_ent[t] = p0 * logf(p0 + 1e-8f) + p1 * logf(p1 + 1e-8f);
    int elo = i0 < i1 ? i0 : i1;
    int ehi = i0 < i1 ? i1 : i0;
    g_topk[2 * t] = elo;
    g_topk[2 * t + 1] = ehi;
    atomicAdd(&g_cnt[elo], 1);
    atomicAdd(&g_cnt[ehi], 1);
  }
}

__global__ void offsets_k() {
  if (threadIdx.x == 0) {
    int o = 0;
    for (int e = 0; e < NE; e++) { g_off[e] = o; o += g_cnt[e]; }
  }
}

__global__ void assign_k() {
  int t = blockIdx.x * blockDim.x + threadIdx.x;
  if (t >= NTOK) return;
#pragma unroll
  for (int k = 0; k < 2; k++) {
    int e = g_topk[2 * t + k];
    int slot = g_off[e] + atomicAdd(&g_cursor[e], 1);
    g_tok_of_slot[slot] = t;
    g_expert_of_slot[slot] = e;
    g_slot_of_tok[2 * t + k] = slot;
  }
}

__global__ void ln_k(const float* __restrict__ lng, const float* __restrict__ lnb) {
  int s = blockIdx.x;
  int e = g_expert_of_slot[s];
  float* row = g_y + (size_t)s * HD;
  int tid = threadIdx.x;
  float4 v = *(const float4*)(row + tid * 4);
  float sum = v.x + v.y + v.z + v.w;
  float sq = v.x * v.x + v.y * v.y + v.z * v.z + v.w * v.w;
  for (int o = 16; o > 0; o >>= 1) {
    sum += __shfl_xor_sync(0xffffffffu, sum, o);
    sq += __shfl_xor_sync(0xffffffffu, sq, o);
  }
  __shared__ float s1[8], s2[8];
  int w = tid >> 5;
  if ((tid & 31) == 0) { s1[w] = sum; s2[w] = sq; }
  __syncthreads();
  float ts = 0.f, tq = 0.f;
#pragma unroll
  for (int i = 0; i < 8; i++) { ts += s1[i]; tq += s2[i]; }
  float mu = ts * (1.f / HD);
  float var = tq * (1.f / HD) - mu * mu;
  float rstd = rsqrtf(var + 1e-5f);
  const float4 g4 = *(const float4*)(lng + e * HD + tid * 4);
  const float4 b4 = *(const float4*)(lnb + e * HD + tid * 4);
  float4 o;
  o.x = (v.x - mu) * rstd * g4.x + b4.x;
  o.y = (v.y - mu) * rstd * g4.y + b4.y;
  o.z = (v.z - mu) * rstd * g4.z + b4.z;
  o.w = (v.w - mu) * rstd * g4.w + b4.w;
  *(float4*)(row + tid * 4) = o;
}

__global__ void combine_k(float* __restrict__ out) {
  int t = blockIdx.x;
  int tid = threadIdx.x;
  int s0 = g_slot_of_tok[2 * t], s1 = g_slot_of_tok[2 * t + 1];
  int e0 = g_topk[2 * t], e1 = g_topk[2 * t + 1];
  float p0 = g_probs[t * NE + e0], p1 = g_probs[t * NE + e1];
  const float4 y0 = *(const float4*)(g_y + (size_t)s0 * HD + tid * 4);
  const float4 y1 = *(const float4*)(g_y + (size_t)s1 * HD + tid * 4);
  float4 o;
  o.x = p0 * y0.x + p1 * y1.x;
  o.y = p0 * y0.y + p1 * y1.y;
  o.z = p0 * y0.z + p1 * y1.z;
  o.w = p0 * y0.w + p1 * y1.w;
  *(float4*)(out + (size_t)t * HD + tid * 4) = o;
}

__global__ void loss_k(float* __restrict__ out, int out_size) {
  __shared__ float red[256];
  float s = 0.f;
  for (int i = threadIdx.x; i < NTOK; i += 256) s += g_ent[i];
  red[threadIdx.x] = s;
  __syncthreads();
  for (int o = 128; o > 0; o >>= 1) {
    if (threadIdx.x < o) red[threadIdx.x] += red[threadIdx.x + o];
    __syncthreads();
  }
  if (threadIdx.x == 0) {
    float loss = -red[0] / (float)NTOK;
    for (int i = NTOK * HD; i < out_size; i++) out[i] = loss;
  }
}

// ================= launch =================
extern "C" void kernel_launch(void* const* d_in, const int* in_sizes, int n_in,
                              void* d_out, int out_size) {
  const float* x           = (const float*)d_in[0];
  const float* te          = (const float*)d_in[1];
  const float* attr_emb    = (const float*)d_in[2];
  const float* attr_proj_w = (const float*)d_in[3];
  const float* attr_proj_b = (const float*)d_in[4];
  const float* gate_w1     = (const float*)d_in[5];
  const float* gate_b1     = (const float*)d_in[6];
  const float* gate_w2     = (const float*)d_in[7];
  const float* gate_b2     = (const float*)d_in[8];
  const float* fc_w1       = (const float*)d_in[9];
  const float* fc_b1       = (const float*)d_in[10];
  const float* fc_w2       = (const float*)d_in[11];
  const float* fc_b2       = (const float*)d_in[12];
  const float* ln_g        = (const float*)d_in[13];
  const float* ln_b        = (const float*)d_in[14];
  const float* r_attr      = (const float*)d_in[15];
  const float* r_in_w      = (const float*)d_in[16];
  const float* r_in_b      = (const float*)d_in[17];
  const float* r_mid_w     = (const float*)d_in[18];
  const float* r_mid_b     = (const float*)d_in[19];
  const float* r_w         = (const float*)d_in[20];
  const float* r_b         = (const float*)d_in[21];
  float* out = (float*)d_out;

  cudaFuncSetAttribute(mgemm_k<2>, cudaFuncAttributeMaxDynamicSharedMemorySize, SMEM_DYN);
  cudaFuncSetAttribute(mgemm_k<3>, cudaFuncAttributeMaxDynamicSharedMemorySize, SMEM_DYN);
  cudaFuncSetAttribute(mgemm_k<4>, cudaFuncAttributeMaxDynamicSharedMemorySize, SMEM_DYN);
  cudaFuncSetAttribute(mgemm_k<5>, cudaFuncAttributeMaxDynamicSharedMemorySize, SMEM_DYN);

  reset_k<<<1, 32>>>();
  ap_k<<<(NE * HD + 255) / 256, 256>>>(attr_emb, attr_proj_w, attr_proj_b);
  c1_k<<<(NE * ID + 255) / 256, 256>>>(gate_w1, gate_b1);

  // router MLP — exact fp32 (protects top-2 decisions; FFMA-ceiling bound)
  fgemm_k<0><<<dim3(R1N / 128, NTOK / 128, 1), 256>>>(x, te, r_in_w, r_in_b, R1N, XTK);
  fgemm_k<1><<<dim3(HD / 128, NTOK / 128, 1), 256>>>(nullptr, nullptr, r_mid_w, r_mid_b, HD, R1N);
  router_head_k<<<NTOK, 256>>>(te, r_attr, r_w, r_b);
  offsets_k<<<1, 32>>>();
  assign_k<<<NTOK / 256, 256>>>();

  // expert FFNs — bf16x3 wmma, 128x256 tiles, double-buffered, in-kernel conv
  mgemm_k<2><<<dim3(ID / 256, NTOK / 128, NE), 256, SMEM_DYN>>>(gate_w1, gate_b1, x, 2 * HD);
  mgemm_k<3><<<dim3(HD / 256, NTOK / 128, NE), 256, SMEM_DYN>>>(gate_w2, gate_b2, x, ID);
  mgemm_k<4><<<dim3(ID / 256, NTOK / 128, NE), 256, SMEM_DYN>>>(fc_w1, fc_b1, x, HD);
  mgemm_k<5><<<dim3(HD / 256, NTOK / 128, NE), 256, SMEM_DYN>>>(fc_w2, fc_b2, x, ID);

  ln_k<<<NSLOT, 256>>>(ln_g, ln_b);
  combine_k<<<NTOK, 256>>>(out);
  loss_k<<<1, 256>>>(out, out_size);
}

// round 14
// speedup vs baseline: 1.5012x; 1.2445x over previous
#include <cuda_runtime.h>
#include <cuda_bf16.h>
#include <mma.h>
#include <math.h>
#include <stdint.h>

using namespace nvcuda;

#define HD    1024
#define AD    256
#define ID    2048
#define NE    8
#define NTOK  4096
#define NSLOT 8192
#define R1N   4096
#define XTK   1280   // H + A

// ================= device-global scratch (fp32 only) =================
__device__ __align__(1024) float g_rh1[(size_t)NTOK * R1N];
__device__ __align__(1024) float g_rh2[(size_t)NTOK * HD];
__device__ __align__(1024) float g_h1a[(size_t)NSLOT * ID];
__device__ __align__(1024) float g_hmid[(size_t)NSLOT * HD];
__device__ __align__(1024) float g_h1b[(size_t)NSLOT * ID];
__device__ __align__(1024) float g_y[(size_t)NSLOT * HD];
__device__ __align__(1024) float g_ap[NE * HD];
__device__ __align__(1024) float g_c1[NE * ID];
__device__ float g_probs[NTOK * NE];
__device__ float g_ent[NTOK];
__device__ int   g_topk[NTOK * 2];
__device__ int   g_slot_of_tok[NTOK * 2];
__device__ int   g_tok_of_slot[NSLOT];
__device__ int   g_expert_of_slot[NSLOT];
__device__ int   g_cnt[NE];
__device__ int   g_off[NE];
__device__ int   g_cursor[NE];

__device__ __forceinline__ void split2(float v, __nv_bfloat16& h, __nv_bfloat16& l) {
  h = __float2bfloat16(v);
  l = __float2bfloat16(v - __bfloat162float(h));
}

// ================= small kernels =================
__global__ void reset_k() {
  int i = threadIdx.x;
  if (i < NE) { g_cnt[i] = 0; g_cursor[i] = 0; }
}

__global__ void ap_k(const float* __restrict__ ae, const float* __restrict__ apw,
                     const float* __restrict__ apb) {
  int idx = blockIdx.x * blockDim.x + threadIdx.x;
  if (idx >= NE * HD) return;
  int e = idx >> 10;
  const float* a = ae + e * AD;
  const float* w = apw + (size_t)idx * AD;
  float s = 0.f;
#pragma unroll 4
  for (int d = 0; d < AD; d += 4) {
    float4 av = *(const float4*)(a + d);
    float4 wv = *(const float4*)(w + d);
    s += av.x * wv.x + av.y * wv.y + av.z * wv.z + av.w * wv.w;
  }
  g_ap[idx] = s + apb[idx];
}

__global__ void c1_k(const float* __restrict__ gw1, const float* __restrict__ gb1) {
  int idx = blockIdx.x * blockDim.x + threadIdx.x;
  if (idx >= NE * ID) return;
  int e = idx / ID;
  const float* w = gw1 + (size_t)idx * (2 * HD) + HD;
  const float* a = g_ap + e * HD;
  float s = 0.f;
#pragma unroll 4
  for (int d = 0; d < HD; d += 4) {
    float4 wv = *(const float4*)(w + d);
    float4 av = *(const float4*)(a + d);
    s += wv.x * av.x + wv.y * av.y + wv.z * av.z + wv.w * av.w;
  }
  g_c1[idx] = s + gb1[idx];
}

// ============ wmma bf16x3 GEMM, 128x256 tile, in-kernel conversion ============
// MODE 0: concat(x,te) @ r_in^T + b -> relu -> g_rh1      (dense, all tokens)
// MODE 1: rh1 @ r_mid^T + b -> relu -> g_rh2              (dense)
// MODE 2: x[tok] @ gw1[:, :H]^T + c1 -> relu -> g_h1a     (routed)
// MODE 3: h1a @ gw2^T + gb2 -> sigmoid mix -> g_hmid      (routed)
// MODE 4: hmid @ fw1^T + fb1 -> relu -> g_h1b             (routed)
// MODE 5: h1b @ fw2^T + fb2 + x -> g_y                    (routed)
#define PITCH  40                       // bf16 elems per smem row (32 + 8 pad)
#define AHO    0
#define ALO    (128 * PITCH)
#define BHO    (256 * PITCH)
#define BLO    (512 * PITCH)
#define SSE    (768 * PITCH)            // stage elems = 61440 B
#define CP2    132                      // fp32 epilogue pitch (128 + 4 pad)
#define SMEM_DYN (2 * SSE * 2 + 1024)

template <int MODE>
__global__ void __launch_bounds__(256, 1)
mgemm_k(const float* __restrict__ W, const float* __restrict__ Bias,
        const float* __restrict__ xin, const float* __restrict__ tein,
        long wstride) {
  constexpr int N = (MODE == 0) ? R1N : (MODE == 2 || MODE == 4) ? ID : HD;
  constexpr int K = (MODE == 0) ? XTK : (MODE == 1) ? R1N
                   : (MODE == 3 || MODE == 5) ? ID : HD;
  constexpr int KT = K >> 5;

  const int e = (MODE >= 2) ? blockIdx.z : 0;
  const int mcount = (MODE >= 2) ? g_cnt[e] : NTOK;
  const int moff = (MODE >= 2) ? g_off[e] : 0;
  const int m0 = blockIdx.y * 128;
  if (m0 >= mcount) return;
  const int n0 = blockIdx.x * 256;

  extern __shared__ char dsm[];
  char* dynp = (char*)(((uintptr_t)dsm + 1023) & ~(uintptr_t)1023);
  __nv_bfloat16* smb = (__nv_bfloat16*)dynp;
  float* csm = (float*)dynp;

  const int tid = threadIdx.x;
  const int wid = tid >> 5;
  const int lrow = tid >> 1;          // 0..127
  const int colb = (tid & 1) << 4;    // 0 or 16

  // ---- fp32 global row pointers ----
  int am = m0 + lrow;
  if (am >= mcount) am = mcount - 1;
  const float* arow;
  const float* tadj = nullptr;        // te row adjusted so (tadj + k) valid for k>=HD
  if (MODE == 0) {
    arow = xin + (size_t)am * HD;
    tadj = tein + (size_t)am * AD - HD;
  } else if (MODE == 1) {
    arow = g_rh1 + (size_t)am * R1N;
  } else {
    const int aslot = moff + am;
    if (MODE == 2)      arow = xin + (size_t)g_tok_of_slot[aslot] * HD;
    else if (MODE == 3) arow = g_h1a + (size_t)aslot * ID;
    else if (MODE == 4) arow = g_hmid + (size_t)aslot * HD;
    else                arow = g_h1b + (size_t)aslot * ID;
  }
  const float* brow0 = W + ((size_t)e * N + n0 + lrow) * (size_t)wstride;
  const float* brow1 = brow0 + (size_t)128 * wstride;

  float4 ar[4], br0[4], br1[4];

#define LOADR(kbase) do { \
  int k0_ = (kbase) + colb; \
  const float* ab_ = (MODE == 0 && k0_ >= HD) ? tadj : arow; \
  _Pragma("unroll") \
  for (int q = 0; q < 4; q++) { \
    ar[q]  = *(const float4*)(ab_   + k0_ + q * 4); \
    br0[q] = *(const float4*)(brow0 + k0_ + q * 4); \
    br1[q] = *(const float4*)(brow1 + k0_ + q * 4); \
  } \
} while (0)

#define SPLIT16(srcp, dsth, dstl) do { \
  const float* f_ = (const float*)(srcp); \
  _Pragma("unroll") \
  for (int i = 0; i < 16; i += 2) { \
    __nv_bfloat16 h0, l0, h1, l1; \
    split2(f_[i], h0, l0); split2(f_[i + 1], h1, l1); \
    *(__nv_bfloat162*)((dsth) + i) = __nv_bfloat162(h0, h1); \
    *(__nv_bfloat162*)((dstl) + i) = __nv_bfloat162(l0, l1); \
  } \
} while (0)

#define STORES(stage) do { \
  __nv_bfloat16* s_ = smb + (stage) * SSE; \
  __nv_bfloat16* as_ = s_ + lrow * PITCH + colb; \
  SPLIT16(ar, as_ + AHO, as_ + ALO); \
  __nv_bfloat16* b0_ = s_ + BHO + lrow * PITCH + colb; \
  SPLIT16(br0, b0_, b0_ + (BLO - BHO)); \
  __nv_bfloat16* b1_ = s_ + BHO + (128 + lrow) * PITCH + colb; \
  SPLIT16(br1, b1_, b1_ + (BLO - BHO)); \
} while (0)

  // ---- wmma tiling: 8 warps = 2(m) x 4(n); warp tile 64m x 64n ----
  const int wm = wid & 1;
  const int wn = wid >> 1;

  wmma::fragment<wmma::accumulator, 16, 16, 16, float> cf[4][4];
#pragma unroll
  for (int mt = 0; mt < 4; mt++)
#pragma unroll
    for (int nt = 0; nt < 4; nt++) wmma::fill_fragment(cf[mt][nt], 0.f);

  LOADR(0);
  STORES(0);
  __syncthreads();

  for (int c = 0; c < KT; c++) {
    if (c + 1 < KT) LOADR((c + 1) << 5);
    const __nv_bfloat16* sb = smb + (c & 1) * SSE;
#pragma unroll
    for (int ks = 0; ks < 2; ks++) {
      wmma::fragment<wmma::matrix_b, 16, 16, 16, __nv_bfloat16, wmma::col_major> bh[4], bl[4];
#pragma unroll
      for (int nt = 0; nt < 4; nt++) {
        const int bo = (wn * 64 + nt * 16) * PITCH + ks * 16;
        wmma::load_matrix_sync(bh[nt], sb + BHO + bo, PITCH);
        wmma::load_matrix_sync(bl[nt], sb + BLO + bo, PITCH);
      }
#pragma unroll
      for (int mt = 0; mt < 4; mt++) {
        const int ao = (wm * 64 + mt * 16) * PITCH + ks * 16;
        wmma::fragment<wmma::matrix_a, 16, 16, 16, __nv_bfloat16, wmma::row_major> ah, al;
        wmma::load_matrix_sync(ah, sb + AHO + ao, PITCH);
        wmma::load_matrix_sync(al, sb + ALO + ao, PITCH);
#pragma unroll
        for (int nt = 0; nt < 4; nt++) {
          wmma::mma_sync(cf[mt][nt], ah, bh[nt], cf[mt][nt]);
          wmma::mma_sync(cf[mt][nt], al, bh[nt], cf[mt][nt]);
          wmma::mma_sync(cf[mt][nt], ah, bl[nt], cf[mt][nt]);
        }
      }
    }
    if (c + 1 < KT) STORES((c + 1) & 1);
    __syncthreads();
  }

  // ---- two-pass epilogue: 128 columns at a time through fp32 smem ----
  const float* bias;
  if (MODE <= 1)      bias = Bias;
  else if (MODE == 2) bias = g_c1 + e * ID;
  else if (MODE == 3) bias = Bias + (size_t)e * HD;
  else if (MODE == 4) bias = Bias + (size_t)e * ID;
  else                bias = Bias + (size_t)e * HD;

  const int r = tid >> 1;
  const int ch = tid & 1;
  const int mi = m0 + r;
  const bool valid = (mi < mcount);
  const int slot = moff + (valid ? mi : 0);
  const int tok = (MODE >= 2) ? g_tok_of_slot[slot] : mi;
  const long orow = (MODE >= 2) ? (long)slot : (long)mi;

#pragma unroll
  for (int hf = 0; hf < 2; hf++) {
    if ((wn >> 1) == hf) {
      const int wnl = wn & 1;
#pragma unroll
      for (int mt = 0; mt < 4; mt++)
#pragma unroll
        for (int nt = 0; nt < 4; nt++)
          wmma::store_matrix_sync(csm + (wm * 64 + mt * 16) * CP2 + wnl * 64 + nt * 16,
                                  cf[mt][nt], CP2, wmma::mem_row_major);
    }
    __syncthreads();
    if (valid) {
      const float* crow = csm + r * CP2 + ch * 64;
      const int nb = n0 + hf * 128 + ch * 64;
#pragma unroll
      for (int j = 0; j < 64; j++) {
        const int n = nb + j;
        float v = crow[j] + bias[n];
        if (MODE == 0) {
          g_rh1[orow * R1N + n] = fmaxf(v, 0.f);
        } else if (MODE == 1) {
          g_rh2[orow * HD + n] = fmaxf(v, 0.f);
        } else if (MODE == 2) {
          g_h1a[orow * ID + n] = fmaxf(v, 0.f);
        } else if (MODE == 3) {
          float g = 1.f / (1.f + expf(-v));
          float xv = xin[(size_t)tok * HD + n];
          float apv = g_ap[e * HD + n];
          g_hmid[orow * HD + n] = xv * g + apv * (1.f - g);
        } else if (MODE == 4) {
          g_h1b[orow * ID + n] = fmaxf(v, 0.f);
        } else {
          g_y[orow * HD + n] = v + xin[(size_t)tok * HD + n];
        }
      }
    }
    if (hf == 0) __syncthreads();
  }
}

// ================= router head / routing / LN / combine / loss =================
__global__ void router_head_k(const float* __restrict__ te,
                              const float* __restrict__ r_attr,
                              const float* __restrict__ r_w,
                              const float* __restrict__ r_b) {
  int t = blockIdx.x;
  int tid = threadIdx.x;
  const float* hrow = g_rh2 + (size_t)t * HD;
  float pe[NE];
#pragma unroll
  for (int e = 0; e < NE; e++) pe[e] = 0.f;
  for (int k = tid; k < HD; k += 256) {
    float hv = hrow[k];
#pragma unroll
    for (int e = 0; e < NE; e++) pe[e] = fmaf(hv, r_w[e * HD + k], pe[e]);
  }
#pragma unroll
  for (int e = 0; e < NE; e++)
    for (int o = 16; o > 0; o >>= 1) pe[e] += __shfl_xor_sync(0xffffffffu, pe[e], o);
  __shared__ float sw[NE][8];
  int w = tid >> 5;
  if ((tid & 31) == 0)
#pragma unroll
    for (int e = 0; e < NE; e++) sw[e][w] = pe[e];
  __syncthreads();
  if (tid == 0) {
    float lg[NE];
    float mx = -1e30f;
    for (int e = 0; e < NE; e++) {
      float s = 0.f;
      for (int i = 0; i < 8; i++) s += sw[e][i];
      s += r_b[e];
      lg[e] = s;
      if (s > mx) mx = s;
    }
    float se = 0.f;
    for (int e = 0; e < NE; e++) { lg[e] = expf(lg[e] - mx); se += lg[e]; }
    float inv = 1.f / se;

    float attr[NE];
    for (int e = 0; e < NE; e++) attr[e] = 0.f;
    const float* tr = te + (size_t)t * AD;
    for (int n = 0; n < 4; n++) {
      float sc[NE];
      for (int e = 0; e < NE; e++) sc[e] = 0.f;
      for (int d = 0; d < 64; d++) {
        float tv = tr[n * 64 + d];
#pragma unroll
        for (int e = 0; e < NE; e++) sc[e] = fmaf(tv, r_attr[d * NE + e], sc[e]);
      }
      float m2 = -1e30f;
      for (int e = 0; e < NE; e++) if (sc[e] > m2) m2 = sc[e];
      float ss = 0.f;
      for (int e = 0; e < NE; e++) { sc[e] = expf(sc[e] - m2); ss += sc[e]; }
      float rr = 0.25f / ss;
      for (int e = 0; e < NE; e++) attr[e] += sc[e] * rr;
    }

    float p[NE];
    for (int e = 0; e < NE; e++) p[e] = lg[e] * inv * attr[e];
    int i0 = 0;
    for (int e = 1; e < NE; e++) if (p[e] > p[i0]) i0 = e;
    int i1 = (i0 == 0) ? 1 : 0;
    for (int e = 0; e < NE; e++) if (e != i0 && p[e] > p[i1]) i1 = e;

    for (int e = 0; e < NE; e++)
      g_probs[t * NE + e] = (e == i0 || e == i1) ? p[e] : 0.f;
    float p0 = p[i0], p1 = p[i1];
    g_ent[t] = p0 * logf(p0 + 1e-8f) + p1 * logf(p1 + 1e-8f);
    int elo = i0 < i1 ? i0 : i1;
    int ehi = i0 < i1 ? i1 : i0;
    g_topk[2 * t] = elo;
    g_topk[2 * t + 1] = ehi;
    atomicAdd(&g_cnt[elo], 1);
    atomicAdd(&g_cnt[ehi], 1);
  }
}

__global__ void offsets_k() {
  if (threadIdx.x == 0) {
    int o = 0;
    for (int e = 0; e < NE; e++) { g_off[e] = o; o += g_cnt[e]; }
  }
}

__global__ void assign_k() {
  int t = blockIdx.x * blockDim.x + threadIdx.x;
  if (t >= NTOK) return;
#pragma unroll
  for (int k = 0; k < 2; k++) {
    int e = g_topk[2 * t + k];
    int slot = g_off[e] + atomicAdd(&g_cursor[e], 1);
    g_tok_of_slot[slot] = t;
    g_expert_of_slot[slot] = e;
    g_slot_of_tok[2 * t + k] = slot;
  }
}

__global__ void ln_k(const float* __restrict__ lng, const float* __restrict__ lnb) {
  int s = blockIdx.x;
  int e = g_expert_of_slot[s];
  float* row = g_y + (size_t)s * HD;
  int tid = threadIdx.x;
  float4 v = *(const float4*)(row + tid * 4);
  float sum = v.x + v.y + v.z + v.w;
  float sq = v.x * v.x + v.y * v.y + v.z * v.z + v.w * v.w;
  for (int o = 16; o > 0; o >>= 1) {
    sum += __shfl_xor_sync(0xffffffffu, sum, o);
    sq += __shfl_xor_sync(0xffffffffu, sq, o);
  }
  __shared__ float s1[8], s2[8];
  int w = tid >> 5;
  if ((tid & 31) == 0) { s1[w] = sum; s2[w] = sq; }
  __syncthreads();
  float ts = 0.f, tq = 0.f;
#pragma unroll
  for (int i = 0; i < 8; i++) { ts += s1[i]; tq += s2[i]; }
  float mu = ts * (1.f / HD);
  float var = tq * (1.f / HD) - mu * mu;
  float rstd = rsqrtf(var + 1e-5f);
  const float4 g4 = *(const float4*)(lng + e * HD + tid * 4);
  const float4 b4 = *(const float4*)(lnb + e * HD + tid * 4);
  float4 o;
  o.x = (v.x - mu) * rstd * g4.x + b4.x;
  o.y = (v.y - mu) * rstd * g4.y + b4.y;
  o.z = (v.z - mu) * rstd * g4.z + b4.z;
  o.w = (v.w - mu) * rstd * g4.w + b4.w;
  *(float4*)(row + tid * 4) = o;
}

__global__ void combine_k(float* __restrict__ out) {
  int t = blockIdx.x;
  int tid = threadIdx.x;
  int s0 = g_slot_of_tok[2 * t], s1 = g_slot_of_tok[2 * t + 1];
  int e0 = g_topk[2 * t], e1 = g_topk[2 * t + 1];
  float p0 = g_probs[t * NE + e0], p1 = g_probs[t * NE + e1];
  const float4 y0 = *(const float4*)(g_y + (size_t)s0 * HD + tid * 4);
  const float4 y1 = *(const float4*)(g_y + (size_t)s1 * HD + tid * 4);
  float4 o;
  o.x = p0 * y0.x + p1 * y1.x;
  o.y = p0 * y0.y + p1 * y1.y;
  o.z = p0 * y0.z + p1 * y1.z;
  o.w = p0 * y0.w + p1 * y1.w;
  *(float4*)(out + (size_t)t * HD + tid * 4) = o;
}

__global__ void loss_k(float* __restrict__ out, int out_size) {
  __shared__ float red[256];
  float s = 0.f;
  for (int i = threadIdx.x; i < NTOK; i += 256) s += g_ent[i];
  red[threadIdx.x] = s;
  __syncthreads();
  for (int o = 128; o > 0; o >>= 1) {
    if (threadIdx.x < o) red[threadIdx.x] += red[threadIdx.x + o];
    __syncthreads();
  }
  if (threadIdx.x == 0) {
    float loss = -red[0] / (float)NTOK;
    for (int i = NTOK * HD; i < out_size; i++) out[i] = loss;
  }
}

// ================= launch =================
extern "C" void kernel_launch(void* const* d_in, const int* in_sizes, int n_in,
                              void* d_out, int out_size) {
  const float* x           = (const float*)d_in[0];
  const float* te          = (const float*)d_in[1];
  const float* attr_emb    = (const float*)d_in[2];
  const float* attr_proj_w = (const float*)d_in[3];
  const float* attr_proj_b = (const float*)d_in[4];
  const float* gate_w1     = (const float*)d_in[5];
  const float* gate_b1     = (const float*)d_in[6];
  const float* gate_w2     = (const float*)d_in[7];
  const float* gate_b2     = (const float*)d_in[8];
  const float* fc_w1       = (const float*)d_in[9];
  const float* fc_b1       = (const float*)d_in[10];
  const float* fc_w2       = (const float*)d_in[11];
  const float* fc_b2       = (const float*)d_in[12];
  const float* ln_g        = (const float*)d_in[13];
  const float* ln_b        = (const float*)d_in[14];
  const float* r_attr      = (const float*)d_in[15];
  const float* r_in_w      = (const float*)d_in[16];
  const float* r_in_b      = (const float*)d_in[17];
  const float* r_mid_w     = (const float*)d_in[18];
  const float* r_mid_b     = (const float*)d_in[19];
  const float* r_w         = (const float*)d_in[20];
  const float* r_b         = (const float*)d_in[21];
  float* out = (float*)d_out;

  cudaFuncSetAttribute(mgemm_k<0>, cudaFuncAttributeMaxDynamicSharedMemorySize, SMEM_DYN);
  cudaFuncSetAttribute(mgemm_k<1>, cudaFuncAttributeMaxDynamicSharedMemorySize, SMEM_DYN);
  cudaFuncSetAttribute(mgemm_k<2>, cudaFuncAttributeMaxDynamicSharedMemorySize, SMEM_DYN);
  cudaFuncSetAttribute(mgemm_k<3>, cudaFuncAttributeMaxDynamicSharedMemorySize, SMEM_DYN);
  cudaFuncSetAttribute(mgemm_k<4>, cudaFuncAttributeMaxDynamicSharedMemorySize, SMEM_DYN);
  cudaFuncSetAttribute(mgemm_k<5>, cudaFuncAttributeMaxDynamicSharedMemorySize, SMEM_DYN);

  reset_k<<<1, 32>>>();
  ap_k<<<(NE * HD + 255) / 256, 256>>>(attr_emb, attr_proj_w, attr_proj_b);
  c1_k<<<(NE * ID + 255) / 256, 256>>>(gate_w1, gate_b1);

  // router MLP — bf16x3 wmma (head / top-k stays exact fp32)
  mgemm_k<0><<<dim3(R1N / 256, NTOK / 128, 1), 256, SMEM_DYN>>>(r_in_w, r_in_b, x, te, XTK);
  mgemm_k<1><<<dim3(HD / 256, NTOK / 128, 1), 256, SMEM_DYN>>>(r_mid_w, r_mid_b, nullptr, nullptr, R1N);
  router_head_k<<<NTOK, 256>>>(te, r_attr, r_w, r_b);
  offsets_k<<<1, 32>>>();
  assign_k<<<NTOK / 256, 256>>>();

  // expert FFNs — bf16x3 wmma, 128x256 tiles (proven R13 engine)
  mgemm_k<2><<<dim3(ID / 256, NTOK / 128, NE), 256, SMEM_DYN>>>(gate_w1, gate_b1, x, nullptr, 2 * HD);
  mgemm_k<3><<<dim3(HD / 256, NTOK / 128, NE), 256, SMEM_DYN>>>(gate_w2, gate_b2, x, nullptr, ID);
  mgemm_k<4><<<dim3(ID / 256, NTOK / 128, NE), 256, SMEM_DYN>>>(fc_w1, fc_b1, x, nullptr, HD);
  mgemm_k<5><<<dim3(HD / 256, NTOK / 128, NE), 256, SMEM_DYN>>>(fc_w2, fc_b2, x, nullptr, ID);

  ln_k<<<NSLOT, 256>>>(ln_g, ln_b);
  combine_k<<<NTOK, 256>>>(out);
  loss_k<<<1, 256>>>(out, out_size);
}